// round 6
// baseline (speedup 1.0000x reference)
#include <cuda_runtime.h>
#include <cuda_fp16.h>

#define NN 50000
#define NE 500000

typedef unsigned long long u64;

// ---- persistent device scratch (zero-initialized at module load) ----
__device__ float  g_Wsg[64 * 256];    // W_src @ W_gate (natural order)
__device__ float  g_Wdg[64 * 256];    // W_dst @ W_gate
__device__ __half g_Wg8h[8 * 256];    // W_enc @ W_gate, packed half2 [(k*4+j)*32+l]
__device__ float  g_bgf[256];         // fused bias (natural order)
__device__ __half g_GsP[NN * 256];    // per-node src-side gate pre (512B/node)
__device__ __half g_Dn[NN * 512];     // per-node dst-side: [0:256)=Gd, [256:512)=z1x,z1y,z1z,z0
__device__ float  g_accP[NN * 256];   // acc: [0:128)=lane*4+{s0,s1,vx0,vx1}; [128:256)=lane*4+{vy0,vy1,vz0,vz1}

// ---- packed f32x2 helpers ----
__device__ __forceinline__ u64 pk(float x, float y) {
    u64 r; asm("mov.b64 %0,{%1,%2};" : "=l"(r) : "f"(x), "f"(y)); return r;
}
__device__ __forceinline__ float2 upk(u64 v) {
    float2 f; asm("mov.b64 {%0,%1},%2;" : "=f"(f.x), "=f"(f.y) : "l"(v)); return f;
}
__device__ __forceinline__ u64 ffma2(u64 a, u64 b, u64 c) {
    u64 r; asm("fma.rn.f32x2 %0,%1,%2,%3;" : "=l"(r) : "l"(a), "l"(b), "l"(c)); return r;
}
__device__ __forceinline__ u64 fmul2(u64 a, u64 b) {
    u64 r; asm("mul.rn.f32x2 %0,%1,%2;" : "=l"(r) : "l"(a), "l"(b)); return r;
}
__device__ __forceinline__ u64 h2f(__half2 h) {
    float2 f = __half22float2(h); return pk(f.x, f.y);
}
__device__ __forceinline__ void red4(float* p, u64 ab, u64 cd) {
    float2 a = upk(ab), c = upk(cd);
    asm volatile("red.global.add.v4.f32 [%0], {%1,%2,%3,%4};"
                 :: "l"(p), "f"(a.x), "f"(a.y), "f"(c.x), "f"(c.y) : "memory");
}

// ---------------------------------------------------------------------------
// 1) fold small weight matrices (all natural channel order; Wg8 packed)
// ---------------------------------------------------------------------------
__global__ void prep_weights(const float* __restrict__ W_src, const float* __restrict__ W_dst,
                             const float* __restrict__ W_enc, const float* __restrict__ W_gate,
                             const float* __restrict__ b_gate, const float* __restrict__ b_enc,
                             const float* __restrict__ b_src, const float* __restrict__ b_dst) {
    int idx = blockIdx.x * blockDim.x + threadIdx.x;
    if (idx < 16384) {
        int k = idx >> 8, c = idx & 255;
        float s = 0.f;
        #pragma unroll 8
        for (int t = 0; t < 64; t++) s += W_src[k * 64 + t] * W_gate[t * 256 + c];
        g_Wsg[idx] = s;
    } else if (idx < 32768) {
        int t0 = idx - 16384;
        int k = t0 >> 8, c = t0 & 255;
        float s = 0.f;
        #pragma unroll 8
        for (int t = 0; t < 64; t++) s += W_dst[k * 64 + t] * W_gate[t * 256 + c];
        g_Wdg[t0] = s;
    } else if (idx < 34816) {
        int t0 = idx - 32768;
        int k = t0 >> 8, c = t0 & 255;
        float s = 0.f;
        #pragma unroll 8
        for (int t = 0; t < 64; t++) s += W_enc[k * 64 + t] * W_gate[t * 256 + c];
        int j = c >> 6, l = (c & 63) >> 1, h = c & 1;
        g_Wg8h[((k * 4 + j) * 32 + l) * 2 + h] = __float2half(s);
    } else if (idx < 35072) {
        int c = idx - 34816;
        float s = b_gate[c];
        for (int t = 0; t < 64; t++) s += (b_enc[t] + b_src[t] + b_dst[t]) * W_gate[t * 256 + c];
        g_bgf[c] = s;
    }
}

// ---------------------------------------------------------------------------
// 2) node precompute (R3 form): Gs = emb @ Wsg -> g_GsP; Gd = emb @ Wdg -> g_Dn[0:256)
// ---------------------------------------------------------------------------
__global__ __launch_bounds__(512) void node_pre(const float* __restrict__ emb) {
    __shared__ float es[16][64];
    int base = blockIdx.x * 16;
    for (int i = threadIdx.x; i < 16 * 64; i += 512) es[i >> 6][i & 63] = emb[base * 64 + i];
    __syncthreads();
    int t = threadIdx.x;
    int c = t & 255;
    const float* W = (t < 256) ? g_Wsg : g_Wdg;
    __half* G = (t < 256) ? g_GsP : g_Dn;
    int stride = (t < 256) ? 256 : 512;
    float a[16];
    #pragma unroll
    for (int n = 0; n < 16; n++) a[n] = 0.f;
    for (int k = 0; k < 64; k++) {
        float wv = W[k * 256 + c];
        #pragma unroll
        for (int n = 0; n < 16; n++) a[n] += es[n][k] * wv;
    }
    #pragma unroll
    for (int n = 0; n < 16; n++) G[(size_t)(base + n) * stride + c] = __float2half(a[n]);
}

// ---------------------------------------------------------------------------
// 3) convert z0/z1 -> fp16 into g_Dn[256:512) per node (natural order, coalesced)
// ---------------------------------------------------------------------------
__global__ void convert_z(const float* __restrict__ z0, const float* __restrict__ z1) {
    const int TOT = NN * 128;           // half2 count
    int i = blockIdx.x * blockDim.x + threadIdx.x;
    int stride = gridDim.x * blockDim.x;
    __half2* Dn2 = (__half2*)g_Dn;
    for (; i < TOT; i += stride) {
        int n = i >> 7, p = i & 127;
        int t = p >> 5, l = p & 31;
        float2 v = (t < 3) ? ((const float2*)z1)[n * 96 + t * 32 + l]
                           : ((const float2*)z0)[n * 32 + l];
        Dn2[(size_t)n * 256 + 128 + t * 32 + l] = __float22half2_rn(v);
    }
}

// ---------------------------------------------------------------------------
// 4) edge kernel: software-pipelined gathers (i+1) + indices (i+2),
//    half2 gathers (1 wavefront each), f32x2 math, red.v4 scatter.
// ---------------------------------------------------------------------------
__global__ __launch_bounds__(256, 2) void edge_kernel(const int* __restrict__ src,
                                                      const int* __restrict__ dst,
                                                      const float* __restrict__ r_ij) {
    const int lane = threadIdx.x & 31;
    const int warp = blockIdx.x * 8 + (threadIdx.x >> 5);
    const int nwarp = gridDim.x * 8;

    // per-lane gate weights in registers (f32x2)
    u64 w[4][8];
    float2 bgj[4];
    {
        const __half2* Wp = (const __half2*)g_Wg8h;
        const float2* bp = (const float2*)g_bgf;
        #pragma unroll
        for (int j = 0; j < 4; j++) {
            bgj[j] = bp[j * 32 + lane];
            #pragma unroll
            for (int k = 0; k < 8; k++) w[j][k] = h2f(Wp[(k * 4 + j) * 32 + lane]);
        }
    }

    const __half2* Gs2 = (const __half2*)g_GsP;
    const __half2* Dn2 = (const __half2*)g_Dn;

    int e0 = warp, e1 = warp + nwarp;
    int s0 = 0, d0 = 0, s1 = 0, d1 = 0;
    __half2 cg[12];
    float rx = 0.f, ry = 0.f, rz = 0.f;

    if (e0 < NE) {
        s0 = __ldg(src + e0); d0 = __ldg(dst + e0);
        rx = __ldg(r_ij + 3 * e0); ry = __ldg(r_ij + 3 * e0 + 1); rz = __ldg(r_ij + 3 * e0 + 2);
        #pragma unroll
        for (int q = 0; q < 4; q++) cg[q] = __ldg(&Gs2[(size_t)s0 * 128 + q * 32 + lane]);
        #pragma unroll
        for (int q = 0; q < 8; q++) cg[4 + q] = __ldg(&Dn2[(size_t)d0 * 256 + q * 32 + lane]);
    }
    if (e1 < NE) { s1 = __ldg(src + e1); d1 = __ldg(dst + e1); }

    while (e0 < NE) {
        // --- prefetch stage: gathers for e1, indices for e2 ---
        __half2 ng[12];
        float nrx = 0.f, nry = 0.f, nrz = 0.f;
        int e2 = e1 + nwarp, s2 = 0, d2 = 0;
        if (e1 < NE) {
            nrx = __ldg(r_ij + 3 * e1); nry = __ldg(r_ij + 3 * e1 + 1); nrz = __ldg(r_ij + 3 * e1 + 2);
            #pragma unroll
            for (int q = 0; q < 4; q++) ng[q] = __ldg(&Gs2[(size_t)s1 * 128 + q * 32 + lane]);
            #pragma unroll
            for (int q = 0; q < 8; q++) ng[4 + q] = __ldg(&Dn2[(size_t)d1 * 256 + q * 32 + lane]);
        }
        if (e2 < NE) { s2 = __ldg(src + e2); d2 = __ldg(dst + e2); }

        // --- compute on e0 ---
        float d2r = fmaf(rx, rx, fmaf(ry, ry, rz * rz));
        float dd = sqrtf(d2r);
        float inv = rsqrtf(fmaf(12.25f, d2r, 1.f));
        float hx = 3.5f * rx * inv, hy = 3.5f * ry * inv, hz = 3.5f * rz * inv;

        u64 g[4];
        #pragma unroll
        for (int j = 0; j < 4; j++) {
            float2 a = __half22float2(cg[j]);
            float2 b = __half22float2(cg[4 + j]);
            g[j] = pk(a.x + b.x + bgj[j].x, a.y + b.y + bgj[j].y);
        }
        #pragma unroll
        for (int k = 0; k < 8; k++) {
            float u = fmaf(dd, 4.f, -(8.f / 7.f) * (float)k);
            float ee = __expf(-u * u);
            u64 r2 = pk(ee, ee);
            #pragma unroll
            for (int j = 0; j < 4; j++) g[j] = ffma2(r2, w[j][k], g[j]);
        }

        u64 ZA = h2f(cg[8]), ZB = h2f(cg[9]), ZC = h2f(cg[10]), Z0 = h2f(cg[11]);
        u64 HX = pk(hx, hx), HY = pk(hy, hy), HZ = pk(hz, hz);

        u64 dot  = ffma2(HZ, ZC, ffma2(HY, ZB, fmul2(HX, ZA)));
        u64 smsg = ffma2(g[1], dot, fmul2(g[0], Z0));
        u64 tt   = fmul2(g[3], Z0);
        u64 vx   = ffma2(HX, tt, fmul2(g[2], ZA));
        u64 vy   = ffma2(HY, tt, fmul2(g[2], ZB));
        u64 vz   = ffma2(HZ, tt, fmul2(g[2], ZC));

        float* base = g_accP + (size_t)s0 * 256 + lane * 4;
        red4(base, smsg, vx);
        red4(base + 128, vy, vz);

        // --- rotate pipeline ---
        e0 = e1; s0 = s1; d0 = d1;
        rx = nrx; ry = nry; rz = nrz;
        #pragma unroll
        for (int q = 0; q < 12; q++) cg[q] = ng[q];
        e1 = e2; s1 = s2; d1 = d2;
    }
}

// ---------------------------------------------------------------------------
// 5) final: out0 = acc_s @ W_s ; out1[:,i,:] = acc_v_i @ W_v ; re-zero acc
//    acc idx for (m,k): ((m>=2)<<7) + 4*(k>>1) + ((m==1||m==3)?2:0) + (k&1)
// ---------------------------------------------------------------------------
__global__ __launch_bounds__(256) void final_kernel(const float* __restrict__ W_s,
                                                    const float* __restrict__ W_v,
                                                    float* __restrict__ out) {
    __shared__ float as[16][256];
    int base = blockIdx.x * 16;
    for (int i = threadIdx.x; i < 16 * 256; i += 256) {
        as[i >> 8][i & 255] = g_accP[(size_t)base * 256 + i];
        g_accP[(size_t)base * 256 + i] = 0.f;     // re-zero for next call
    }
    __syncthreads();
    int o = threadIdx.x;
    int c = o & 63;
    int m = (o < 64) ? 0 : 1 + ((o - 64) >> 6);
    const float* W = (o < 64) ? W_s : W_v;
    int off = ((m >= 2) ? 128 : 0) + ((m == 1 || m == 3) ? 2 : 0);
    float a[16];
    #pragma unroll
    for (int n = 0; n < 16; n++) a[n] = 0.f;
    for (int k = 0; k < 64; k++) {
        float wv = W[k * 64 + c];
        int idx = off + 4 * (k >> 1) + (k & 1);
        #pragma unroll
        for (int n = 0; n < 16; n++) a[n] += as[n][idx] * wv;
    }
    if (m == 0) {
        #pragma unroll
        for (int n = 0; n < 16; n++) out[(base + n) * 64 + c] = a[n];
    } else {
        int i = m - 1;
        #pragma unroll
        for (int n = 0; n < 16; n++)
            out[NN * 64 + ((base + n) * 3 + i) * 64 + c] = a[n];
    }
}

// ---------------------------------------------------------------------------
extern "C" void kernel_launch(void* const* d_in, const int* in_sizes, int n_in,
                              void* d_out, int out_size) {
    const int*   src    = (const int*)d_in[0];
    const int*   dst    = (const int*)d_in[1];
    const float* r_ij   = (const float*)d_in[2];
    const float* z_0    = (const float*)d_in[3];
    const float* z_1    = (const float*)d_in[4];
    const float* emb    = (const float*)d_in[5];
    const float* W_enc  = (const float*)d_in[6];
    const float* b_enc  = (const float*)d_in[7];
    const float* W_src  = (const float*)d_in[8];
    const float* b_src  = (const float*)d_in[9];
    const float* W_dst  = (const float*)d_in[10];
    const float* b_dst  = (const float*)d_in[11];
    const float* W_gate = (const float*)d_in[12];
    const float* b_gate = (const float*)d_in[13];
    const float* W_s    = (const float*)d_in[14];
    const float* W_v    = (const float*)d_in[15];
    float* out = (float*)d_out;

    convert_z<<<2048, 256>>>(z_0, z_1);
    prep_weights<<<137, 256>>>(W_src, W_dst, W_enc, W_gate, b_gate, b_enc, b_src, b_dst);
    node_pre<<<NN / 16, 512>>>(emb);
    edge_kernel<<<888, 256>>>(src, dst, r_ij);
    final_kernel<<<NN / 16, 256>>>(W_s, W_v, out);
}

// round 7
// speedup vs baseline: 2.2019x; 2.2019x over previous
#include <cuda_runtime.h>
#include <cuda_fp16.h>

#define NN 50000
#define NE 500000

typedef unsigned long long u64;

// ---- persistent device scratch (zero-initialized at module load) ----
__device__ float  g_Wsg[64 * 256];    // W_src @ W_gate (natural order)
__device__ float  g_Wdg[64 * 256];    // W_dst @ W_gate
__device__ __half g_Wg8h[8 * 256];    // W_enc @ W_gate, packed half2 [(k*4+j)*32+l]
__device__ float  g_bgf[256];         // fused bias (natural order)
__device__ __half g_GsP[NN * 256];    // per-node src-side gate pre (512B/node)
__device__ __half g_Dn[NN * 512];     // per-node dst-side: [0:256)=Gd, [256:512)=z1x,z1y,z1z,z0
__device__ float  g_accP[NN * 256];   // acc: [0:128)=lane*4+{s0,s1,vx0,vx1}; [128:256)=lane*4+{vy0,vy1,vz0,vz1}

// ---- packed f32x2 helpers ----
__device__ __forceinline__ u64 pk(float x, float y) {
    u64 r; asm("mov.b64 %0,{%1,%2};" : "=l"(r) : "f"(x), "f"(y)); return r;
}
__device__ __forceinline__ float2 upk(u64 v) {
    float2 f; asm("mov.b64 {%0,%1},%2;" : "=f"(f.x), "=f"(f.y) : "l"(v)); return f;
}
__device__ __forceinline__ u64 ffma2(u64 a, u64 b, u64 c) {
    u64 r; asm("fma.rn.f32x2 %0,%1,%2,%3;" : "=l"(r) : "l"(a), "l"(b), "l"(c)); return r;
}
__device__ __forceinline__ u64 fmul2(u64 a, u64 b) {
    u64 r; asm("mul.rn.f32x2 %0,%1,%2;" : "=l"(r) : "l"(a), "l"(b)); return r;
}
__device__ __forceinline__ u64 h2f(__half2 h) {
    float2 f = __half22float2(h); return pk(f.x, f.y);
}
__device__ __forceinline__ void red4(float* p, u64 ab, u64 cd) {
    float2 a = upk(ab), c = upk(cd);
    asm volatile("red.global.add.v4.f32 [%0], {%1,%2,%3,%4};"
                 :: "l"(p), "f"(a.x), "f"(a.y), "f"(c.x), "f"(c.y) : "memory");
}

// ---------------------------------------------------------------------------
// 1) fold small weight matrices (natural channel order; Wg8 packed for lanes)
// ---------------------------------------------------------------------------
__global__ void prep_weights(const float* __restrict__ W_src, const float* __restrict__ W_dst,
                             const float* __restrict__ W_enc, const float* __restrict__ W_gate,
                             const float* __restrict__ b_gate, const float* __restrict__ b_enc,
                             const float* __restrict__ b_src, const float* __restrict__ b_dst) {
    int idx = blockIdx.x * blockDim.x + threadIdx.x;
    if (idx < 16384) {
        int k = idx >> 8, c = idx & 255;
        float s = 0.f;
        #pragma unroll 8
        for (int t = 0; t < 64; t++) s += W_src[k * 64 + t] * W_gate[t * 256 + c];
        g_Wsg[idx] = s;
    } else if (idx < 32768) {
        int t0 = idx - 16384;
        int k = t0 >> 8, c = t0 & 255;
        float s = 0.f;
        #pragma unroll 8
        for (int t = 0; t < 64; t++) s += W_dst[k * 64 + t] * W_gate[t * 256 + c];
        g_Wdg[t0] = s;
    } else if (idx < 34816) {
        int t0 = idx - 32768;
        int k = t0 >> 8, c = t0 & 255;
        float s = 0.f;
        #pragma unroll 8
        for (int t = 0; t < 64; t++) s += W_enc[k * 64 + t] * W_gate[t * 256 + c];
        int j = c >> 6, l = (c & 63) >> 1, h = c & 1;
        g_Wg8h[((k * 4 + j) * 32 + l) * 2 + h] = __float2half(s);
    } else if (idx < 35072) {
        int c = idx - 34816;
        float s = b_gate[c];
        for (int t = 0; t < 64; t++) s += (b_enc[t] + b_src[t] + b_dst[t]) * W_gate[t * 256 + c];
        g_bgf[c] = s;
    }
}

// ---------------------------------------------------------------------------
// 2) node precompute: Gs = emb @ Wsg -> g_GsP; Gd = emb @ Wdg -> g_Dn[0:256)
// ---------------------------------------------------------------------------
__global__ __launch_bounds__(512) void node_pre(const float* __restrict__ emb) {
    __shared__ float es[16][64];
    int base = blockIdx.x * 16;
    for (int i = threadIdx.x; i < 16 * 64; i += 512) es[i >> 6][i & 63] = emb[base * 64 + i];
    __syncthreads();
    int t = threadIdx.x;
    int c = t & 255;
    const float* W = (t < 256) ? g_Wsg : g_Wdg;
    __half* G = (t < 256) ? g_GsP : g_Dn;
    int stride = (t < 256) ? 256 : 512;
    float a[16];
    #pragma unroll
    for (int n = 0; n < 16; n++) a[n] = 0.f;
    for (int k = 0; k < 64; k++) {
        float wv = W[k * 256 + c];
        #pragma unroll
        for (int n = 0; n < 16; n++) a[n] += es[n][k] * wv;
    }
    #pragma unroll
    for (int n = 0; n < 16; n++) G[(size_t)(base + n) * stride + c] = __float2half(a[n]);
}

// ---------------------------------------------------------------------------
// 3) fused: zero accumulator (float4 streaming) + pack z0/z1 -> g_Dn[256:512)
// ---------------------------------------------------------------------------
__global__ void zero_convert(const float* __restrict__ z0, const float* __restrict__ z1) {
    const int T0 = NN * 64;            // float4 zeroes for acc
    const int T1 = T0 + NN * 128;      // half2 packs for z
    int i = blockIdx.x * blockDim.x + threadIdx.x;
    int stride = gridDim.x * blockDim.x;
    __half2* Dn2 = (__half2*)g_Dn;
    for (; i < T1; i += stride) {
        if (i < T0) {
            ((float4*)g_accP)[i] = make_float4(0.f, 0.f, 0.f, 0.f);
        } else {
            int j = i - T0;
            int n = j >> 7, p = j & 127;
            int t = p >> 5, l = p & 31;
            float2 v = (t < 3) ? ((const float2*)z1)[n * 96 + t * 32 + l]
                               : ((const float2*)z0)[n * 32 + l];
            Dn2[(size_t)n * 256 + 128 + t * 32 + l] = __float22half2_rn(v);
        }
    }
}

// ---------------------------------------------------------------------------
// 4) edge kernel (unchanged from R6 — measured 169us): software-pipelined
//    gathers (i+1) + indices (i+2), half2 gathers, f32x2 math, red.v4 scatter.
// ---------------------------------------------------------------------------
__global__ __launch_bounds__(256, 2) void edge_kernel(const int* __restrict__ src,
                                                      const int* __restrict__ dst,
                                                      const float* __restrict__ r_ij) {
    const int lane = threadIdx.x & 31;
    const int warp = blockIdx.x * 8 + (threadIdx.x >> 5);
    const int nwarp = gridDim.x * 8;

    // per-lane gate weights in registers (f32x2)
    u64 w[4][8];
    float2 bgj[4];
    {
        const __half2* Wp = (const __half2*)g_Wg8h;
        const float2* bp = (const float2*)g_bgf;
        #pragma unroll
        for (int j = 0; j < 4; j++) {
            bgj[j] = bp[j * 32 + lane];
            #pragma unroll
            for (int k = 0; k < 8; k++) w[j][k] = h2f(Wp[(k * 4 + j) * 32 + lane]);
        }
    }

    const __half2* Gs2 = (const __half2*)g_GsP;
    const __half2* Dn2 = (const __half2*)g_Dn;

    int e0 = warp, e1 = warp + nwarp;
    int s0 = 0, d0 = 0, s1 = 0, d1 = 0;
    __half2 cg[12];
    float rx = 0.f, ry = 0.f, rz = 0.f;

    if (e0 < NE) {
        s0 = __ldg(src + e0); d0 = __ldg(dst + e0);
        rx = __ldg(r_ij + 3 * e0); ry = __ldg(r_ij + 3 * e0 + 1); rz = __ldg(r_ij + 3 * e0 + 2);
        #pragma unroll
        for (int q = 0; q < 4; q++) cg[q] = __ldg(&Gs2[(size_t)s0 * 128 + q * 32 + lane]);
        #pragma unroll
        for (int q = 0; q < 8; q++) cg[4 + q] = __ldg(&Dn2[(size_t)d0 * 256 + q * 32 + lane]);
    }
    if (e1 < NE) { s1 = __ldg(src + e1); d1 = __ldg(dst + e1); }

    while (e0 < NE) {
        // --- prefetch stage: gathers for e1, indices for e2 ---
        __half2 ng[12];
        float nrx = 0.f, nry = 0.f, nrz = 0.f;
        int e2 = e1 + nwarp, s2 = 0, d2 = 0;
        if (e1 < NE) {
            nrx = __ldg(r_ij + 3 * e1); nry = __ldg(r_ij + 3 * e1 + 1); nrz = __ldg(r_ij + 3 * e1 + 2);
            #pragma unroll
            for (int q = 0; q < 4; q++) ng[q] = __ldg(&Gs2[(size_t)s1 * 128 + q * 32 + lane]);
            #pragma unroll
            for (int q = 0; q < 8; q++) ng[4 + q] = __ldg(&Dn2[(size_t)d1 * 256 + q * 32 + lane]);
        }
        if (e2 < NE) { s2 = __ldg(src + e2); d2 = __ldg(dst + e2); }

        // --- compute on e0 ---
        float d2r = fmaf(rx, rx, fmaf(ry, ry, rz * rz));
        float dd = sqrtf(d2r);
        float inv = rsqrtf(fmaf(12.25f, d2r, 1.f));
        float hx = 3.5f * rx * inv, hy = 3.5f * ry * inv, hz = 3.5f * rz * inv;

        u64 g[4];
        #pragma unroll
        for (int j = 0; j < 4; j++) {
            float2 a = __half22float2(cg[j]);
            float2 b = __half22float2(cg[4 + j]);
            g[j] = pk(a.x + b.x + bgj[j].x, a.y + b.y + bgj[j].y);
        }
        #pragma unroll
        for (int k = 0; k < 8; k++) {
            float u = fmaf(dd, 4.f, -(8.f / 7.f) * (float)k);
            float ee = __expf(-u * u);
            u64 r2 = pk(ee, ee);
            #pragma unroll
            for (int j = 0; j < 4; j++) g[j] = ffma2(r2, w[j][k], g[j]);
        }

        u64 ZA = h2f(cg[8]), ZB = h2f(cg[9]), ZC = h2f(cg[10]), Z0 = h2f(cg[11]);
        u64 HX = pk(hx, hx), HY = pk(hy, hy), HZ = pk(hz, hz);

        u64 dot  = ffma2(HZ, ZC, ffma2(HY, ZB, fmul2(HX, ZA)));
        u64 smsg = ffma2(g[1], dot, fmul2(g[0], Z0));
        u64 tt   = fmul2(g[3], Z0);
        u64 vx   = ffma2(HX, tt, fmul2(g[2], ZA));
        u64 vy   = ffma2(HY, tt, fmul2(g[2], ZB));
        u64 vz   = ffma2(HZ, tt, fmul2(g[2], ZC));

        float* base = g_accP + (size_t)s0 * 256 + lane * 4;
        red4(base, smsg, vx);
        red4(base + 128, vy, vz);

        // --- rotate pipeline ---
        e0 = e1; s0 = s1; d0 = d1;
        rx = nrx; ry = nry; rz = nrz;
        #pragma unroll
        for (int q = 0; q < 12; q++) cg[q] = ng[q];
        e1 = e2; s1 = s2; d1 = d2;
    }
}

// ---------------------------------------------------------------------------
// 5) final: out0 = acc_s @ W_s ; out1[:,i,:] = acc_v_i @ W_v  (no re-zero)
//    acc idx for (m,k): ((m>=2)?128:0) + 4*(k>>1) + ((m==1||m==3)?2:0) + (k&1)
// ---------------------------------------------------------------------------
__global__ __launch_bounds__(256) void final_kernel(const float* __restrict__ W_s,
                                                    const float* __restrict__ W_v,
                                                    float* __restrict__ out) {
    __shared__ float as[16][256];
    int base = blockIdx.x * 16;
    for (int i = threadIdx.x; i < 16 * 256; i += 256)
        as[i >> 8][i & 255] = g_accP[(size_t)base * 256 + i];
    __syncthreads();
    int o = threadIdx.x;
    int c = o & 63;
    int m = (o < 64) ? 0 : 1 + ((o - 64) >> 6);
    const float* W = (o < 64) ? W_s : W_v;
    int off = ((m >= 2) ? 128 : 0) + ((m == 1 || m == 3) ? 2 : 0);
    float a[16];
    #pragma unroll
    for (int n = 0; n < 16; n++) a[n] = 0.f;
    for (int k = 0; k < 64; k++) {
        float wv = W[k * 64 + c];
        int idx = off + 4 * (k >> 1) + (k & 1);
        #pragma unroll
        for (int n = 0; n < 16; n++) a[n] += as[n][idx] * wv;
    }
    if (m == 0) {
        #pragma unroll
        for (int n = 0; n < 16; n++) out[(base + n) * 64 + c] = a[n];
    } else {
        int i = m - 1;
        #pragma unroll
        for (int n = 0; n < 16; n++)
            out[NN * 64 + ((base + n) * 3 + i) * 64 + c] = a[n];
    }
}

// ---------------------------------------------------------------------------
extern "C" void kernel_launch(void* const* d_in, const int* in_sizes, int n_in,
                              void* d_out, int out_size) {
    const int*   src    = (const int*)d_in[0];
    const int*   dst    = (const int*)d_in[1];
    const float* r_ij   = (const float*)d_in[2];
    const float* z_0    = (const float*)d_in[3];
    const float* z_1    = (const float*)d_in[4];
    const float* emb    = (const float*)d_in[5];
    const float* W_enc  = (const float*)d_in[6];
    const float* b_enc  = (const float*)d_in[7];
    const float* W_src  = (const float*)d_in[8];
    const float* b_src  = (const float*)d_in[9];
    const float* W_dst  = (const float*)d_in[10];
    const float* b_dst  = (const float*)d_in[11];
    const float* W_gate = (const float*)d_in[12];
    const float* b_gate = (const float*)d_in[13];
    const float* W_s    = (const float*)d_in[14];
    const float* W_v    = (const float*)d_in[15];
    float* out = (float*)d_out;

    zero_convert<<<2048, 256>>>(z_0, z_1);
    prep_weights<<<137, 256>>>(W_src, W_dst, W_enc, W_gate, b_gate, b_enc, b_src, b_dst);
    node_pre<<<NN / 16, 512>>>(emb);
    edge_kernel<<<888, 256>>>(src, dst, r_ij);
    final_kernel<<<NN / 16, 256>>>(W_s, W_v, out);
}